// round 4
// baseline (speedup 1.0000x reference)
#include <cuda_runtime.h>

#define FULLMASK 0xFFFFFFFFu

// One warp processes TWO 4096-element segments of the same (b,c) row
// (segments p and p+2), giving two independent scan chains whose shuffle/FMA
// latencies interleave (ILP). Segments are independent via a decayed warm-up
// halo (g^halo < 1e-10 => exact at fp32; clamps to row start / exact fallback
// if g ~ 1). Tile = 256 elements (lane owns 8 contiguous = two float4s):
//   per-lane 8-elem chain -> warp Kogge-Stone over lane tails (ratio g^8)
//   -> cross-tile carry with g^256. Outputs are reconstructed with the exact
//   serial recurrence y_i = g*y_{i-1} + (1-g)*x_i seeded from the scan state.
__global__ void __launch_bounds__(256, 4)
ema_dual_kernel(const float4* __restrict__ x4,
                const float* __restrict__ w,
                float4* __restrict__ out4,
                int Cdim, int T, int nrows, int nseg)
{
    constexpr int SEG_TILES = 16;              // 16 * 256 = 4096 elems/segment
    const int warp  = threadIdx.x >> 5;
    const int lane  = threadIdx.x & 31;
    const int npair = nseg >> 1;               // warp covers 2 segments
    const int gw    = blockIdx.x * 8 + warp;
    const int row   = gw / npair;
    const int p     = gw - row * npair;
    if (row >= nrows) return;

    const float g   = __ldg(&w[row % Cdim]);
    const float omg = 1.0f - g;
    const float g1  = g;
    const float g4  = g1 * g1 * g1 * g1;
    const float g8  = g4 * g4;                 // lane-step ratio
    const float g16 = g8 * g8;
    const float g32 = g16 * g16;
    const float g64 = g32 * g32;
    const float g128 = g64 * g64;
    const float g256 = g128 * g128;            // tile-step ratio

    // g^(8*lane)
    float pl = 1.0f;
    if (lane & 1)  pl *= g8;
    if (lane & 2)  pl *= g16;
    if (lane & 4)  pl *= g32;
    if (lane & 8)  pl *= g64;
    if (lane & 16) pl *= g128;

    // warm-up tiles: g^(256*wt) < 1e-10, exact fallback if g ~ 1
    int wt_base;
    if (g > 0.0f && g < 0.9999f)
        wt_base = (int)((-23.03f * (1.0f / 256.0f)) / __logf(g)) + 1;
    else
        wt_base = 0x3fffffff;

    const int t0A = p * SEG_TILES;
    const int t0B = (p + npair) * SEG_TILES;
    const int wtA = min(wt_base, t0A);
    const int wtB = min(wt_base, t0B);

    const float4* __restrict__ xin  = x4   + (size_t)row * (T >> 2);
    float4*       __restrict__ yout = out4 + (size_t)row * (T >> 2);

    float CA = 0.0f, CB = 0.0f;

    // ---- warm-up prologues (no stores; wt is 0 or 1 in the normal case) ----
    #pragma unroll 1
    for (int t = t0A - wtA; t < t0A; ++t) {
        const int b = t * 64 + 2 * lane;
        const float4 a0 = __ldcs(xin + b);
        const float4 a1 = __ldcs(xin + b + 1);
        float l = a0.x * omg;
        l = fmaf(g1, l, a0.y * omg); l = fmaf(g1, l, a0.z * omg);
        l = fmaf(g1, l, a0.w * omg); l = fmaf(g1, l, a1.x * omg);
        l = fmaf(g1, l, a1.y * omg); l = fmaf(g1, l, a1.z * omg);
        l = fmaf(g1, l, a1.w * omg);
        float v = l, tv;
        tv = __shfl_up_sync(FULLMASK, v, 1);  if (lane >= 1)  v = fmaf(g8,   tv, v);
        tv = __shfl_up_sync(FULLMASK, v, 2);  if (lane >= 2)  v = fmaf(g16,  tv, v);
        tv = __shfl_up_sync(FULLMASK, v, 4);  if (lane >= 4)  v = fmaf(g32,  tv, v);
        tv = __shfl_up_sync(FULLMASK, v, 8);  if (lane >= 8)  v = fmaf(g64,  tv, v);
        tv = __shfl_up_sync(FULLMASK, v, 16); if (lane >= 16) v = fmaf(g128, tv, v);
        CA = fmaf(g256, CA, __shfl_sync(FULLMASK, v, 31));
    }
    #pragma unroll 1
    for (int t = t0B - wtB; t < t0B; ++t) {
        const int b = t * 64 + 2 * lane;
        const float4 a0 = __ldcs(xin + b);
        const float4 a1 = __ldcs(xin + b + 1);
        float l = a0.x * omg;
        l = fmaf(g1, l, a0.y * omg); l = fmaf(g1, l, a0.z * omg);
        l = fmaf(g1, l, a0.w * omg); l = fmaf(g1, l, a1.x * omg);
        l = fmaf(g1, l, a1.y * omg); l = fmaf(g1, l, a1.z * omg);
        l = fmaf(g1, l, a1.w * omg);
        float v = l, tv;
        tv = __shfl_up_sync(FULLMASK, v, 1);  if (lane >= 1)  v = fmaf(g8,   tv, v);
        tv = __shfl_up_sync(FULLMASK, v, 2);  if (lane >= 2)  v = fmaf(g16,  tv, v);
        tv = __shfl_up_sync(FULLMASK, v, 4);  if (lane >= 4)  v = fmaf(g32,  tv, v);
        tv = __shfl_up_sync(FULLMASK, v, 8);  if (lane >= 8)  v = fmaf(g64,  tv, v);
        tv = __shfl_up_sync(FULLMASK, v, 16); if (lane >= 16) v = fmaf(g128, tv, v);
        CB = fmaf(g256, CB, __shfl_sync(FULLMASK, v, 31));
    }

    // ---- fused main loop: both segments, branch-free, stores every tile ----
    const int baseA = t0A * 64 + 2 * lane;
    const int baseB = t0B * 64 + 2 * lane;

    float4 a0 = __ldcs(xin + baseA), a1 = __ldcs(xin + baseA + 1);
    float4 b0 = __ldcs(xin + baseB), b1 = __ldcs(xin + baseB + 1);

    #pragma unroll 1
    for (int t = 0; t < SEG_TILES; ++t) {
        float4 na0 = a0, na1 = a1, nb0 = b0, nb1 = b1;
        if (t + 1 < SEG_TILES) {
            const int ia = baseA + (t + 1) * 64;
            const int ib = baseB + (t + 1) * 64;
            na0 = __ldcs(xin + ia); na1 = __ldcs(xin + ia + 1);
            nb0 = __ldcs(xin + ib); nb1 = __ldcs(xin + ib + 1);
        }

        // lane-local chain tails (A and B interleave)
        float la = a0.x * omg;
        float lb = b0.x * omg;
        la = fmaf(g1, la, a0.y * omg);  lb = fmaf(g1, lb, b0.y * omg);
        la = fmaf(g1, la, a0.z * omg);  lb = fmaf(g1, lb, b0.z * omg);
        la = fmaf(g1, la, a0.w * omg);  lb = fmaf(g1, lb, b0.w * omg);
        la = fmaf(g1, la, a1.x * omg);  lb = fmaf(g1, lb, b1.x * omg);
        la = fmaf(g1, la, a1.y * omg);  lb = fmaf(g1, lb, b1.y * omg);
        la = fmaf(g1, la, a1.z * omg);  lb = fmaf(g1, lb, b1.z * omg);
        la = fmaf(g1, la, a1.w * omg);  lb = fmaf(g1, lb, b1.w * omg);

        // interleaved Kogge-Stone scans, ratio g^8
        float va = la, vb = lb, ta, tb;
        ta = __shfl_up_sync(FULLMASK, va, 1);
        tb = __shfl_up_sync(FULLMASK, vb, 1);
        if (lane >= 1)  { va = fmaf(g8,   ta, va); vb = fmaf(g8,   tb, vb); }
        ta = __shfl_up_sync(FULLMASK, va, 2);
        tb = __shfl_up_sync(FULLMASK, vb, 2);
        if (lane >= 2)  { va = fmaf(g16,  ta, va); vb = fmaf(g16,  tb, vb); }
        ta = __shfl_up_sync(FULLMASK, va, 4);
        tb = __shfl_up_sync(FULLMASK, vb, 4);
        if (lane >= 4)  { va = fmaf(g32,  ta, va); vb = fmaf(g32,  tb, vb); }
        ta = __shfl_up_sync(FULLMASK, va, 8);
        tb = __shfl_up_sync(FULLMASK, vb, 8);
        if (lane >= 8)  { va = fmaf(g64,  ta, va); vb = fmaf(g64,  tb, vb); }
        ta = __shfl_up_sync(FULLMASK, va, 16);
        tb = __shfl_up_sync(FULLMASK, vb, 16);
        if (lane >= 16) { va = fmaf(g128, ta, va); vb = fmaf(g128, tb, vb); }

        // exclusive carries + EMA state just before this lane's first element
        float cLa = __shfl_up_sync(FULLMASK, va, 1);
        float cLb = __shfl_up_sync(FULLMASK, vb, 1);
        if (lane == 0) { cLa = 0.0f; cLb = 0.0f; }
        float ya = fmaf(pl, CA, cLa);   // y at lane position -1 (segment A)
        float yb = fmaf(pl, CB, cLb);   // y at lane position -1 (segment B)

        // exact serial reconstruction of the 8 outputs per lane
        float4 oa0, oa1, ob0, ob1;
        ya = fmaf(g1, ya, a0.x * omg);  yb = fmaf(g1, yb, b0.x * omg);
        oa0.x = ya;                     ob0.x = yb;
        ya = fmaf(g1, ya, a0.y * omg);  yb = fmaf(g1, yb, b0.y * omg);
        oa0.y = ya;                     ob0.y = yb;
        ya = fmaf(g1, ya, a0.z * omg);  yb = fmaf(g1, yb, b0.z * omg);
        oa0.z = ya;                     ob0.z = yb;
        ya = fmaf(g1, ya, a0.w * omg);  yb = fmaf(g1, yb, b0.w * omg);
        oa0.w = ya;                     ob0.w = yb;
        ya = fmaf(g1, ya, a1.x * omg);  yb = fmaf(g1, yb, b1.x * omg);
        oa1.x = ya;                     ob1.x = yb;
        ya = fmaf(g1, ya, a1.y * omg);  yb = fmaf(g1, yb, b1.y * omg);
        oa1.y = ya;                     ob1.y = yb;
        ya = fmaf(g1, ya, a1.z * omg);  yb = fmaf(g1, yb, b1.z * omg);
        oa1.z = ya;                     ob1.z = yb;
        ya = fmaf(g1, ya, a1.w * omg);  yb = fmaf(g1, yb, b1.w * omg);
        oa1.w = ya;                     ob1.w = yb;

        const int oa = baseA + t * 64;
        const int ob = baseB + t * 64;
        __stcs(yout + oa,     oa0);
        __stcs(yout + oa + 1, oa1);
        __stcs(yout + ob,     ob0);
        __stcs(yout + ob + 1, ob1);

        // cross-tile carries
        CA = fmaf(g256, CA, __shfl_sync(FULLMASK, va, 31));
        CB = fmaf(g256, CB, __shfl_sync(FULLMASK, vb, 31));

        a0 = na0; a1 = na1; b0 = nb0; b1 = nb1;
    }
}

extern "C" void kernel_launch(void* const* d_in, const int* in_sizes, int n_in,
                              void* d_out, int out_size)
{
    const float4* x4 = (const float4*)d_in[0];
    const float*  w  = (const float*)d_in[1];
    float4* out4 = (float4*)d_out;

    const int Cdim  = in_sizes[1];          // 512
    const int T     = 16384;                // fixed problem shape
    const int nrows = in_sizes[0] / T;      // B*C = 4096
    const int nseg  = T / 4096;             // 4 segments per row, 2 per warp

    const int total_warps     = nrows * (nseg / 2);   // 8192
    const int warps_per_block = 8;
    dim3 block(32 * warps_per_block);
    dim3 grid((total_warps + warps_per_block - 1) / warps_per_block);
    ema_dual_kernel<<<grid, block>>>(x4, w, out4, Cdim, T, nrows, nseg);
}

// round 5
// speedup vs baseline: 1.0035x; 1.0035x over previous
#include <cuda_runtime.h>

#define FULLMASK 0xFFFFFFFFu

// One warp per 4096-element SEGMENT of a (b,c) row. Segments independent via
// a decayed warm-up halo (g^halo < 1e-10 => exact at fp32; clamps to row
// start / exact full-scan fallback if g ~ 1). Tile = 256 elements: lane owns
// 8 contiguous elements (two float4s).
//   per-lane 8-elem chain tail -> warp Kogge-Stone over lane tails (ratio
//   g^8) -> cross-tile carry with g^256 -> outputs reconstructed with the
//   exact serial recurrence y_i = g*y_{i-1} + (1-g)*x_i seeded from the scan.
// Register-dieted (no prefetch, no live prefix values) to reach 6 blocks/SM
// = 48 warps/SM; latency hiding comes from occupancy, not per-warp MLP.
__global__ void __launch_bounds__(256, 6)
ema_scan_lean_kernel(const float4* __restrict__ x4,
                     const float* __restrict__ w,
                     float4* __restrict__ out4,
                     int Cdim, int T, int nrows, int nseg)
{
    constexpr int SEG_TILES = 16;             // 16 * 256 = 4096 elems/segment
    const int warp = threadIdx.x >> 5;
    const int lane = threadIdx.x & 31;
    const int gw   = blockIdx.x * 8 + warp;   // global segment id
    const int row  = gw / nseg;
    const int seg  = gw - row * nseg;
    if (row >= nrows) return;

    const float g   = __ldg(&w[row % Cdim]);
    const float omg = 1.0f - g;

    const float g2   = g * g;
    const float g4   = g2 * g2;
    const float g8   = g4 * g4;               // lane-step ratio
    const float g16  = g8 * g8;
    const float g32  = g16 * g16;
    const float g64  = g32 * g32;
    const float g128 = g64 * g64;
    const float g256 = g128 * g128;           // tile-step ratio

    // g^(8*lane) by binary decomposition
    float pl = 1.0f;
    if (lane & 1)  pl *= g8;
    if (lane & 2)  pl *= g16;
    if (lane & 4)  pl *= g32;
    if (lane & 8)  pl *= g64;
    if (lane & 16) pl *= g128;

    // warm-up tiles: g^(256*wt) < 1e-10; exact fallback if g ~ 1
    int wt;
    if (g > 0.0f && g < 0.9999f)
        wt = (int)((-23.03f * (1.0f / 256.0f)) / __logf(g)) + 1;
    else
        wt = 0x3fffffff;
    const int seg_tile0 = seg * SEG_TILES;
    if (wt > seg_tile0) wt = seg_tile0;
    if (wt < 0) wt = 0;

    const float4* __restrict__ xin  = x4   + (size_t)row * (T >> 2);
    float4*       __restrict__ yout = out4 + (size_t)row * (T >> 2);

    const int tile_begin = seg_tile0 - wt;
    const int count      = wt + SEG_TILES;

    float C = 0.0f;

    #pragma unroll 1
    for (int t = 0; t < count; ++t) {
        const int base = (tile_begin + t) * 64 + 2 * lane;
        const float4 a0 = __ldcs(xin + base);
        const float4 a1 = __ldcs(xin + base + 1);

        // per-lane chain tail over 8 contiguous elements
        float l = a0.x * omg;
        l = fmaf(g, l, a0.y * omg);
        l = fmaf(g, l, a0.z * omg);
        l = fmaf(g, l, a0.w * omg);
        l = fmaf(g, l, a1.x * omg);
        l = fmaf(g, l, a1.y * omg);
        l = fmaf(g, l, a1.z * omg);
        l = fmaf(g, l, a1.w * omg);

        // warp inclusive scan of lane tails, ratio g^8
        float v = l, tv;
        tv = __shfl_up_sync(FULLMASK, v, 1);  if (lane >= 1)  v = fmaf(g8,   tv, v);
        tv = __shfl_up_sync(FULLMASK, v, 2);  if (lane >= 2)  v = fmaf(g16,  tv, v);
        tv = __shfl_up_sync(FULLMASK, v, 4);  if (lane >= 4)  v = fmaf(g32,  tv, v);
        tv = __shfl_up_sync(FULLMASK, v, 8);  if (lane >= 8)  v = fmaf(g64,  tv, v);
        tv = __shfl_up_sync(FULLMASK, v, 16); if (lane >= 16) v = fmaf(g128, tv, v);

        // exclusive carry from earlier lanes
        float cL = __shfl_up_sync(FULLMASK, v, 1);
        if (lane == 0) cL = 0.0f;

        if (t >= wt) {
            // EMA state just before this lane's first element
            float y = fmaf(pl, C, cL);
            float4 o0, o1;
            y = fmaf(g, y, a0.x * omg);  o0.x = y;
            y = fmaf(g, y, a0.y * omg);  o0.y = y;
            y = fmaf(g, y, a0.z * omg);  o0.z = y;
            y = fmaf(g, y, a0.w * omg);  o0.w = y;
            y = fmaf(g, y, a1.x * omg);  o1.x = y;
            y = fmaf(g, y, a1.y * omg);  o1.y = y;
            y = fmaf(g, y, a1.z * omg);  o1.z = y;
            y = fmaf(g, y, a1.w * omg);  o1.w = y;
            __stcs(yout + base,     o0);
            __stcs(yout + base + 1, o1);
        }

        // cross-tile carry
        C = fmaf(g256, C, __shfl_sync(FULLMASK, v, 31));
    }
}

extern "C" void kernel_launch(void* const* d_in, const int* in_sizes, int n_in,
                              void* d_out, int out_size)
{
    const float4* x4 = (const float4*)d_in[0];
    const float*  w  = (const float*)d_in[1];
    float4* out4 = (float4*)d_out;

    const int Cdim  = in_sizes[1];          // 512
    const int T     = 16384;                // fixed problem shape
    const int nrows = in_sizes[0] / T;      // B*C = 4096
    const int nseg  = T / 4096;             // 4 segments per row

    const int total_warps     = nrows * nseg;   // 16384
    const int warps_per_block = 8;
    dim3 block(32 * warps_per_block);
    dim3 grid((total_warps + warps_per_block - 1) / warps_per_block);
    ema_scan_lean_kernel<<<grid, block>>>(x4, w, out4, Cdim, T, nrows, nseg);
}

// round 7
// speedup vs baseline: 1.0670x; 1.0633x over previous
#include <cuda_runtime.h>

#define FULLMASK 0xFFFFFFFFu

// One warp per 4096-element SEGMENT of a (b,c) row. Segments independent via
// a decayed warm-up halo (g^halo < 1e-10 => exact at fp32; clamps to row
// start / exact full-scan fallback if g ~ 1). Tile = 256 elements: lane owns
// 8 contiguous elements (two float4s).
//   per-lane 8-elem chain tail -> warp Kogge-Stone over lane tails (ratio
//   g^8) -> cross-tile carry with g^256 -> outputs reconstructed with the
//   exact serial recurrence seeded from the scan state.
// Register-prefetches the next tile (keeps 4 LDG.128 in flight on one
// contiguous stream) while staying lean enough for 10 blocks/SM at 128 thr.
__global__ void __launch_bounds__(128, 10)
ema_scan_pf_kernel(const float4* __restrict__ x4,
                   const float* __restrict__ w,
                   float4* __restrict__ out4,
                   int Cdim, int T, int nrows, int nseg)
{
    constexpr int SEG_TILES = 16;             // 16 * 256 = 4096 elems/segment
    const int warp = threadIdx.x >> 5;
    const int lane = threadIdx.x & 31;
    const int gw   = blockIdx.x * 4 + warp;   // global segment id
    const int row  = gw / nseg;
    const int seg  = gw - row * nseg;
    if (row >= nrows) return;

    const float g   = __ldg(&w[row % Cdim]);
    const float omg = 1.0f - g;

    const float g2   = g * g;
    const float g4   = g2 * g2;
    const float g8   = g4 * g4;               // lane-step ratio
    const float g16  = g8 * g8;
    const float g32  = g16 * g16;
    const float g64  = g32 * g32;
    const float g128 = g64 * g64;
    const float g256 = g128 * g128;           // tile-step ratio

    // g^(8*lane) by binary decomposition
    float pl = 1.0f;
    if (lane & 1)  pl *= g8;
    if (lane & 2)  pl *= g16;
    if (lane & 4)  pl *= g32;
    if (lane & 8)  pl *= g64;
    if (lane & 16) pl *= g128;

    // warm-up tiles: g^(256*wt) < 1e-10; exact fallback if g ~ 1
    int wt;
    if (g > 0.0f && g < 0.9999f)
        wt = (int)((-23.03f * (1.0f / 256.0f)) / __logf(g)) + 1;
    else
        wt = 0x3fffffff;
    const int seg_tile0 = seg * SEG_TILES;
    if (wt > seg_tile0) wt = seg_tile0;
    if (wt < 0) wt = 0;

    const float4* __restrict__ xin  = x4   + (size_t)row * (T >> 2);
    float4*       __restrict__ yout = out4 + (size_t)row * (T >> 2);

    const int tile_begin = seg_tile0 - wt;
    const int count      = wt + SEG_TILES;

    float C = 0.0f;

    int base = tile_begin * 64 + 2 * lane;
    float4 a0 = __ldcs(xin + base);
    float4 a1 = __ldcs(xin + base + 1);

    #pragma unroll 1
    for (int t = 0; t < count; ++t) {
        // prefetch next tile while this one is scanned
        float4 n0 = a0, n1 = a1;
        if (t + 1 < count) {
            n0 = __ldcs(xin + base + 64);
            n1 = __ldcs(xin + base + 65);
        }

        // per-lane chain tail over 8 contiguous elements
        float l = a0.x * omg;
        l = fmaf(g, l, a0.y * omg);
        l = fmaf(g, l, a0.z * omg);
        l = fmaf(g, l, a0.w * omg);
        l = fmaf(g, l, a1.x * omg);
        l = fmaf(g, l, a1.y * omg);
        l = fmaf(g, l, a1.z * omg);
        l = fmaf(g, l, a1.w * omg);

        // warp inclusive scan of lane tails, ratio g^8
        float v = l, tv;
        tv = __shfl_up_sync(FULLMASK, v, 1);  if (lane >= 1)  v = fmaf(g8,   tv, v);
        tv = __shfl_up_sync(FULLMASK, v, 2);  if (lane >= 2)  v = fmaf(g16,  tv, v);
        tv = __shfl_up_sync(FULLMASK, v, 4);  if (lane >= 4)  v = fmaf(g32,  tv, v);
        tv = __shfl_up_sync(FULLMASK, v, 8);  if (lane >= 8)  v = fmaf(g64,  tv, v);
        tv = __shfl_up_sync(FULLMASK, v, 16); if (lane >= 16) v = fmaf(g128, tv, v);

        // exclusive carry from earlier lanes
        float cL = __shfl_up_sync(FULLMASK, v, 1);
        if (lane == 0) cL = 0.0f;

        if (t >= wt) {
            // EMA state just before this lane's first element, then exact
            // serial reconstruction of the 8 outputs
            float y = fmaf(pl, C, cL);
            float4 o0, o1;
            y = fmaf(g, y, a0.x * omg);  o0.x = y;
            y = fmaf(g, y, a0.y * omg);  o0.y = y;
            y = fmaf(g, y, a0.z * omg);  o0.z = y;
            y = fmaf(g, y, a0.w * omg);  o0.w = y;
            y = fmaf(g, y, a1.x * omg);  o1.x = y;
            y = fmaf(g, y, a1.y * omg);  o1.y = y;
            y = fmaf(g, y, a1.z * omg);  o1.z = y;
            y = fmaf(g, y, a1.w * omg);  o1.w = y;
            __stcs(yout + base,     o0);
            __stcs(yout + base + 1, o1);
        }

        // cross-tile carry
        C = fmaf(g256, C, __shfl_sync(FULLMASK, v, 31));

        a0 = n0; a1 = n1;
        base += 64;
    }
}

extern "C" void kernel_launch(void* const* d_in, const int* in_sizes, int n_in,
                              void* d_out, int out_size)
{
    const float4* x4 = (const float4*)d_in[0];
    const float*  w  = (const float*)d_in[1];
    float4* out4 = (float4*)d_out;

    const int Cdim  = in_sizes[1];          // 512
    const int T     = 16384;                // fixed problem shape
    const int nrows = in_sizes[0] / T;      // B*C = 4096
    const int nseg  = T / 4096;             // 4 segments per row

    const int total_warps     = nrows * nseg;   // 16384
    const int warps_per_block = 4;
    dim3 block(32 * warps_per_block);           // 128 threads
    dim3 grid((total_warps + warps_per_block - 1) / warps_per_block);
    ema_scan_pf_kernel<<<grid, block>>>(x4, w, out4, Cdim, T, nrows, nseg);
}